// round 6
// baseline (speedup 1.0000x reference)
#include <cuda_runtime.h>
#include <cuda_fp16.h>

#define TSTEPS 30
#define BLOCK  64
#define NBATCH 262144

constexpr int WTOT = 2432;                       // prepped weight floats in smem

typedef unsigned long long u64;
typedef unsigned int       u32;

// ---------- packed fp32x2 helpers (sm_103a FFMA2 path) ----------
__device__ __forceinline__ u64 ffma2(u64 a, u64 b, u64 c) {
    u64 d; asm("fma.rn.f32x2 %0, %1, %2, %3;" : "=l"(d) : "l"(a), "l"(b), "l"(c)); return d;
}
__device__ __forceinline__ u64 splat2(float v) {
    u64 d; asm("mov.b64 %0, {%1, %1};" : "=l"(d) : "f"(v)); return d;
}
__device__ __forceinline__ u64 pack2(float x, float y) {
    u64 d; asm("mov.b64 %0, {%1, %2};" : "=l"(d) : "f"(x), "f"(y)); return d;
}
__device__ __forceinline__ float2 unpack2(u64 v) {
    float2 r; asm("mov.b64 {%0, %1}, %2;" : "=f"(r.x), "=f"(r.y) : "l"(v)); return r;
}
__device__ __forceinline__ float tanhfast(float x){ float r; asm("tanh.approx.f32 %0, %1;" : "=f"(r) : "f"(x)); return r; }

__device__ __forceinline__ int comboOff(int c){ return c < 2 ? c*128 : 256 + (c-2)*272; }

union H4 { u64 u; __half2 h[2]; };
union H2 { u32 u; __half2 h; };
__device__ __forceinline__ u64 h4pack(__half2 a, __half2 b){ H4 t; t.h[0]=a; t.h[1]=b; return t.u; }

// Slot order (rz-merged): s=2u+g, g in {r,z}, unit u (s<10); s=10..14 n-gate; s=15 pad.
// r/z rows scaled 0.5 (gi+gh merged): sig(v)=0.5+0.5*tanh(v/2); n rows unscaled.

// ---------- per-direction constants: W_hh (5x16) + biases in registers ----------
__device__ __forceinline__ void load_dir(const float* wbase, int D,
                                         u64* whhr, u64* bA, u64* bGn, u64* bHn)
{
    const float4* wh4 = (const float4*)(wbase + 16*D);
#pragma unroll
    for (int k = 0; k < 5; ++k)
#pragma unroll
        for (int qq = 0; qq < 4; ++qq) {
            float4 a = wh4[k*4+qq];
            whhr[k*8+qq*2+0] = pack2(a.x, a.y);
            whhr[k*8+qq*2+1] = pack2(a.z, a.w);
        }
    const float4* b4 = (const float4*)(wbase + 16*D + 80);   // gi-side bias
    float4 c0 = b4[0], c1 = b4[1], c2 = b4[2], c3 = b4[3];
    bA[0] = pack2(c0.x,c0.y); bA[1] = pack2(c0.z,c0.w);
    bA[2] = pack2(c1.x,c1.y); bA[3] = pack2(c1.z,c1.w);
    bA[4] = pack2(c2.x,c2.y);
    bGn[0] = pack2(c2.z,c2.w); bGn[1] = pack2(c3.x,c3.y); bGn[2] = pack2(c3.z,c3.w);
    const float4* b5 = (const float4*)(wbase + 16*D + 96);   // gh-side n bias
    float4 d2 = b5[2], d3 = b5[3];
    bHn[0] = pack2(d2.z,d2.w); bHn[1] = pack2(d3.x,d3.y); bHn[2] = pack2(d3.z,d3.w);
}

// ---------- one GRU timestep for TWO elements (weight loads amortized) ----------
template<int D>
__device__ __forceinline__ void gru_step2(const float4* __restrict__ wih4,
                                          const u64* whhr, const u64* bA,
                                          const u64* bGn, const u64* bHn,
                                          const float* xin0, const float* xin1,
                                          float* h0, float* h1)
{
    u64 A0[5], Gn0[3], Hn0[3], A1[5], Gn1[3], Hn1[3];
#pragma unroll
    for (int p = 0; p < 5; ++p) { A0[p] = bA[p]; A1[p] = bA[p]; }
#pragma unroll
    for (int p = 0; p < 3; ++p) {
        Gn0[p] = bGn[p]; Hn0[p] = bHn[p];
        Gn1[p] = bGn[p]; Hn1[p] = bHn[p];
    }
#pragma unroll
    for (int k = 0; k < D; ++k) {
        u64 xs0 = splat2(xin0[k]);
        u64 xs1 = splat2(xin1[k]);
        float4 w0 = wih4[k*4+0], w1 = wih4[k*4+1], w2 = wih4[k*4+2], w3 = wih4[k*4+3];
        u64 p0 = pack2(w0.x,w0.y), p1 = pack2(w0.z,w0.w);
        u64 p2 = pack2(w1.x,w1.y), p3 = pack2(w1.z,w1.w);
        u64 p4 = pack2(w2.x,w2.y), p5 = pack2(w2.z,w2.w);
        u64 p6 = pack2(w3.x,w3.y), p7 = pack2(w3.z,w3.w);
        A0[0]  = ffma2(p0, xs0, A0[0]);   A1[0]  = ffma2(p0, xs1, A1[0]);
        A0[1]  = ffma2(p1, xs0, A0[1]);   A1[1]  = ffma2(p1, xs1, A1[1]);
        A0[2]  = ffma2(p2, xs0, A0[2]);   A1[2]  = ffma2(p2, xs1, A1[2]);
        A0[3]  = ffma2(p3, xs0, A0[3]);   A1[3]  = ffma2(p3, xs1, A1[3]);
        A0[4]  = ffma2(p4, xs0, A0[4]);   A1[4]  = ffma2(p4, xs1, A1[4]);
        Gn0[0] = ffma2(p5, xs0, Gn0[0]);  Gn1[0] = ffma2(p5, xs1, Gn1[0]);
        Gn0[1] = ffma2(p6, xs0, Gn0[1]);  Gn1[1] = ffma2(p6, xs1, Gn1[1]);
        Gn0[2] = ffma2(p7, xs0, Gn0[2]);  Gn1[2] = ffma2(p7, xs1, Gn1[2]);
    }
#pragma unroll
    for (int k = 0; k < 5; ++k) {
        u64 hs0 = splat2(h0[k]);
        u64 hs1 = splat2(h1[k]);
        A0[0]  = ffma2(whhr[k*8+0], hs0, A0[0]);   A1[0]  = ffma2(whhr[k*8+0], hs1, A1[0]);
        A0[1]  = ffma2(whhr[k*8+1], hs0, A0[1]);   A1[1]  = ffma2(whhr[k*8+1], hs1, A1[1]);
        A0[2]  = ffma2(whhr[k*8+2], hs0, A0[2]);   A1[2]  = ffma2(whhr[k*8+2], hs1, A1[2]);
        A0[3]  = ffma2(whhr[k*8+3], hs0, A0[3]);   A1[3]  = ffma2(whhr[k*8+3], hs1, A1[3]);
        A0[4]  = ffma2(whhr[k*8+4], hs0, A0[4]);   A1[4]  = ffma2(whhr[k*8+4], hs1, A1[4]);
        Hn0[0] = ffma2(whhr[k*8+5], hs0, Hn0[0]);  Hn1[0] = ffma2(whhr[k*8+5], hs1, Hn1[0]);
        Hn0[1] = ffma2(whhr[k*8+6], hs0, Hn0[1]);  Hn1[1] = ffma2(whhr[k*8+6], hs1, Hn1[1]);
        Hn0[2] = ffma2(whhr[k*8+7], hs0, Hn0[2]);  Hn1[2] = ffma2(whhr[k*8+7], hs1, Hn1[2]);
    }
    float gn0[6], hn0[6], gn1[6], hn1[6];
#pragma unroll
    for (int p = 0; p < 3; ++p) {
        float2 a = unpack2(Gn0[p]); gn0[2*p] = a.x; gn0[2*p+1] = a.y;
        float2 c = unpack2(Hn0[p]); hn0[2*p] = c.x; hn0[2*p+1] = c.y;
        float2 e = unpack2(Gn1[p]); gn1[2*p] = e.x; gn1[2*p+1] = e.y;
        float2 f = unpack2(Hn1[p]); hn1[2*p] = f.x; hn1[2*p+1] = f.y;
    }
#pragma unroll
    for (int u = 0; u < 5; ++u) {
        float2 rz0 = unpack2(A0[u]);
        float2 rz1 = unpack2(A1[u]);
        float r0 = fmaf(0.5f, tanhfast(rz0.x), 0.5f);
        float r1 = fmaf(0.5f, tanhfast(rz1.x), 0.5f);
        float z0 = fmaf(0.5f, tanhfast(rz0.y), 0.5f);
        float z1 = fmaf(0.5f, tanhfast(rz1.y), 0.5f);
        float n0 = tanhfast(fmaf(r0, hn0[u], gn0[u]));
        float n1 = tanhfast(fmaf(r1, hn1[u], gn1[u]));
        h0[u] = fmaf(z0, h0[u] - n0, n0);
        h1[u] = fmaf(z1, h1[u] - n1, n1);
    }
}

// fp16 triplet -> 10 floats (fwd 0..4, bwd 5..9)
__device__ __forceinline__ void cvt_in(u64 ra, u64 rb, u32 rc, float* xin)
{
    H4 a, b; H2 c; a.u = ra; b.u = rb; c.u = rc;
    float2 p0 = __half22float2(a.h[0]);
    float2 p1 = __half22float2(a.h[1]);
    float2 p2 = __half22float2(b.h[0]);
    float2 p3 = __half22float2(b.h[1]);
    float2 p4 = __half22float2(c.h);
    xin[0]=p0.x; xin[1]=p0.y; xin[2]=p1.x; xin[3]=p1.y; xin[4]=p2.x;
    xin[5]=p2.y; xin[6]=p3.x; xin[7]=p3.y; xin[8]=p4.x; xin[9]=p4.y;
}

// pack helpers for the merged (fwd+bwd) activation entry
__device__ __forceinline__ void pack_entry(const float* hb, u64 fa, u32 fcu,
                                           u64& oa, u64& ob, u32& oc)
{
    H2 fc; fc.u = fcu;
    oa = fa;
    ob = h4pack(__halves2half2(__low2half(fc.h), __float2half_rn(hb[0])),
                __floats2half2_rn(hb[1], hb[2]));
    H2 t; t.h = __floats2half2_rn(hb[3], hb[4]);
    oc = t.u;
}

__global__ void __launch_bounds__(BLOCK, 4)
gru_kernel(const float* __restrict__ x,
           const float* __restrict__ wih0, const float* __restrict__ whh0,
           const float* __restrict__ bih0, const float* __restrict__ bhh0,
           const float* __restrict__ wihU, const float* __restrict__ whhU,
           const float* __restrict__ bihU, const float* __restrict__ bhhU,
           float* __restrict__ out)
{
    extern __shared__ float smem[];
    float* sw   = smem;                                   // [2432]
    u64*   bufA = (u64*)(smem + WTOT);                    // [T*BLOCK] elem0 (f0..f3)
    u64*   bufB = bufA + TSTEPS*BLOCK;                    // [T*BLOCK] elem0 (f4,b0,b1,b2)
    u32*   bufC = (u32*)(bufB + TSTEPS*BLOCK);            // [T*BLOCK] elem0 (b3,b4)
    const int tid = threadIdx.x;

    // ---- cooperative weight prep: transpose to slot layout, pre-scale, merge biases ----
    for (int c = 0; c < 10; ++c) {
        int l = c >> 1, d = c & 1;
        int D = l ? 10 : 1;
        float* w = sw + comboOff(c);
        for (int i = tid; i < 16*D; i += BLOCK) {           // wihT[k][slot]
            int k = i >> 4, s = i & 15;
            float v = 0.f;
            if (s < 15) {
                int  j  = (s < 10) ? ((s & 1)*5 + (s >> 1)) : s;
                float sc = (s < 10) ? 0.5f : 1.0f;
                v = sc * (l == 0 ? wih0[d*15 + j]
                                 : wihU[(((l-1)*2 + d)*15 + j)*10 + k]);
            }
            w[i] = v;
        }
        float* wh = w + 16*D;
        for (int i = tid; i < 80; i += BLOCK) {             // whhT[k][slot]
            int k = i >> 4, s = i & 15;
            float v = 0.f;
            if (s < 15) {
                int  j  = (s < 10) ? ((s & 1)*5 + (s >> 1)) : s;
                float sc = (s < 10) ? 0.5f : 1.0f;
                v = sc * (l == 0 ? whh0[(d*15 + j)*5 + k]
                                 : whhU[(((l-1)*2 + d)*15 + j)*5 + k]);
            }
            wh[i] = v;
        }
        float* bg = wh + 80;                                // gi-side bias
        for (int s = tid; s < 16; s += BLOCK) {
            float v = 0.f;
            if (s < 15) {
                int  j  = (s < 10) ? ((s & 1)*5 + (s >> 1)) : s;
                float sc = (s < 10) ? 0.5f : 1.0f;
                float bi = l == 0 ? bih0[d*15 + j] : bihU[((l-1)*2 + d)*15 + j];
                float bh = l == 0 ? bhh0[d*15 + j] : bhhU[((l-1)*2 + d)*15 + j];
                v = sc * (s < 10 ? (bi + bh) : bi);
            }
            bg[s] = v;
        }
        float* bh2 = bg + 16;                               // gh-side n bias
        for (int s = tid; s < 16; s += BLOCK) {
            float v = 0.f;
            if (s >= 10 && s < 15)
                v = l == 0 ? bhh0[d*15 + s] : bhhU[((l-1)*2 + d)*15 + s];
            bh2[s] = v;
        }
    }
    __syncthreads();
    // smem buf slots are thread-private from here on; no further syncs needed

    const int b0 = blockIdx.x * (2*BLOCK) + tid;   // element 0 (smem buf)
    const int b1 = b0 + BLOCK;                     // element 1 (local buf)
    const float* xrow0 = x + (size_t)b0 * TSTEPS;
    const float* xrow1 = x + (size_t)b1 * TSTEPS;

    u64 whhr[40], bA[5], bGn[3], bHn[3];
    float h0[5], h1[5];

    // elem1 activation buffer in local memory (entry t at index t+1; pads at 0 and 31)
    u64 lbufA[TSTEPS+2], lbufB[TSTEPS+2];
    u32 lbufC[TSTEPS+2];
    // fwd staging for both elements
    u64 fscrA0[TSTEPS], fscrA1[TSTEPS];
    u32 fscrC0[TSTEPS], fscrC1[TSTEPS];

    // ===== layer 0 (D=1): fwd -> fscr, bwd -> merged entries =====
    {
        const float* w = sw + comboOff(0);
        load_dir(w, 1, whhr, bA, bGn, bHn);
        const float4* wih4 = (const float4*)w;
#pragma unroll
        for (int u = 0; u < 5; ++u) { h0[u] = 0.f; h1[u] = 0.f; }
#pragma unroll 1
        for (int t = 0; t < TSTEPS; ++t) {
            float xin0[1] = { xrow0[t] };
            float xin1[1] = { xrow1[t] };
            gru_step2<1>(wih4, whhr, bA, bGn, bHn, xin0, xin1, h0, h1);
            fscrA0[t] = h4pack(__floats2half2_rn(h0[0], h0[1]), __floats2half2_rn(h0[2], h0[3]));
            fscrA1[t] = h4pack(__floats2half2_rn(h1[0], h1[1]), __floats2half2_rn(h1[2], h1[3]));
            H2 f0; f0.h = __floats2half2_rn(h0[4], 0.f); fscrC0[t] = f0.u;
            H2 f1; f1.h = __floats2half2_rn(h1[4], 0.f); fscrC1[t] = f1.u;
        }
    }
    {
        const float* w = sw + comboOff(1);
        load_dir(w, 1, whhr, bA, bGn, bHn);
        const float4* wih4 = (const float4*)w;
#pragma unroll
        for (int u = 0; u < 5; ++u) { h0[u] = 0.f; h1[u] = 0.f; }
#pragma unroll 1
        for (int tt = 0; tt < TSTEPS; ++tt) {
            int t = TSTEPS-1-tt;
            u64 fa0 = fscrA0[t]; u32 fc0 = fscrC0[t];
            u64 fa1 = fscrA1[t]; u32 fc1 = fscrC1[t];
            float xin0[1] = { xrow0[t] };
            float xin1[1] = { xrow1[t] };
            gru_step2<1>(wih4, whhr, bA, bGn, bHn, xin0, xin1, h0, h1);
            u64 oa, ob; u32 oc;
            pack_entry(h0, fa0, fc0, oa, ob, oc);
            bufA[t*BLOCK+tid] = oa; bufB[t*BLOCK+tid] = ob; bufC[t*BLOCK+tid] = oc;
            pack_entry(h1, fa1, fc1, oa, ob, oc);
            lbufA[t+1] = oa; lbufB[t+1] = ob; lbufC[t+1] = oc;
        }
    }

    // ===== layers 1..3: fwd -> fscr, bwd overwrites buffers in place =====
#pragma unroll 1
    for (int l = 1; l < 4; ++l) {
        {   // fwd: elem1 input prefetched one step ahead
            const float* w = sw + comboOff(2*l);
            load_dir(w, 10, whhr, bA, bGn, bHn);
            const float4* wih4 = (const float4*)w;
#pragma unroll
            for (int u = 0; u < 5; ++u) { h0[u] = 0.f; h1[u] = 0.f; }
            u64 ra = lbufA[1], rb = lbufB[1]; u32 rc = lbufC[1];
#pragma unroll 1
            for (int t = 0; t < TSTEPS; ++t) {
                u64 ca = ra, cb = rb; u32 cc = rc;
                ra = lbufA[t+2]; rb = lbufB[t+2]; rc = lbufC[t+2];  // pad at 31
                float xin0[10], xin1[10];
                cvt_in(bufA[t*BLOCK+tid], bufB[t*BLOCK+tid], bufC[t*BLOCK+tid], xin0);
                cvt_in(ca, cb, cc, xin1);
                gru_step2<10>(wih4, whhr, bA, bGn, bHn, xin0, xin1, h0, h1);
                fscrA0[t] = h4pack(__floats2half2_rn(h0[0], h0[1]), __floats2half2_rn(h0[2], h0[3]));
                fscrA1[t] = h4pack(__floats2half2_rn(h1[0], h1[1]), __floats2half2_rn(h1[2], h1[3]));
                H2 f0; f0.h = __floats2half2_rn(h0[4], 0.f); fscrC0[t] = f0.u;
                H2 f1; f1.h = __floats2half2_rn(h1[4], 0.f); fscrC1[t] = f1.u;
            }
        }
        {   // bwd: elem1 input prefetched one step ahead (downward)
            const float* w = sw + comboOff(2*l+1);
            load_dir(w, 10, whhr, bA, bGn, bHn);
            const float4* wih4 = (const float4*)w;
#pragma unroll
            for (int u = 0; u < 5; ++u) { h0[u] = 0.f; h1[u] = 0.f; }
            u64 ra = lbufA[TSTEPS], rb = lbufB[TSTEPS]; u32 rc = lbufC[TSTEPS];
#pragma unroll 1
            for (int tt = 0; tt < TSTEPS; ++tt) {
                int t = TSTEPS-1-tt;
                u64 ca = ra, cb = rb; u32 cc = rc;
                ra = lbufA[t]; rb = lbufB[t]; rc = lbufC[t];        // pad at 0
                u64 fa0 = fscrA0[t]; u32 fc0 = fscrC0[t];
                u64 fa1 = fscrA1[t]; u32 fc1 = fscrC1[t];
                float xin0[10], xin1[10];
                cvt_in(bufA[t*BLOCK+tid], bufB[t*BLOCK+tid], bufC[t*BLOCK+tid], xin0);
                cvt_in(ca, cb, cc, xin1);
                gru_step2<10>(wih4, whhr, bA, bGn, bHn, xin0, xin1, h0, h1);
                u64 oa, ob; u32 oc;
                pack_entry(h0, fa0, fc0, oa, ob, oc);
                bufA[t*BLOCK+tid] = oa; bufB[t*BLOCK+tid] = ob; bufC[t*BLOCK+tid] = oc;
                pack_entry(h1, fa1, fc1, oa, ob, oc);
                lbufA[t+1] = oa; lbufB[t+1] = ob; lbufC[t+1] = oc;
            }
        }
    }

    // ===== layer 4: fwd full (keep final h only); bwd = ONE step at t=T-1 =====
    float hf0[5], hf1[5];
    {
        const float* w = sw + comboOff(8);
        load_dir(w, 10, whhr, bA, bGn, bHn);
        const float4* wih4 = (const float4*)w;
#pragma unroll
        for (int u = 0; u < 5; ++u) { h0[u] = 0.f; h1[u] = 0.f; }
        u64 ra = lbufA[1], rb = lbufB[1]; u32 rc = lbufC[1];
#pragma unroll 1
        for (int t = 0; t < TSTEPS; ++t) {
            u64 ca = ra, cb = rb; u32 cc = rc;
            ra = lbufA[t+2]; rb = lbufB[t+2]; rc = lbufC[t+2];
            float xin0[10], xin1[10];
            cvt_in(bufA[t*BLOCK+tid], bufB[t*BLOCK+tid], bufC[t*BLOCK+tid], xin0);
            cvt_in(ca, cb, cc, xin1);
            gru_step2<10>(wih4, whhr, bA, bGn, bHn, xin0, xin1, h0, h1);
        }
#pragma unroll
        for (int u = 0; u < 5; ++u) { hf0[u] = h0[u]; hf1[u] = h1[u]; }
    }
    {
        const float* w = sw + comboOff(9);
        load_dir(w, 10, whhr, bA, bGn, bHn);
        const float4* wih4 = (const float4*)w;
#pragma unroll
        for (int u = 0; u < 5; ++u) { h0[u] = 0.f; h1[u] = 0.f; }
        int t = TSTEPS-1;
        float xin0[10], xin1[10];
        cvt_in(bufA[t*BLOCK+tid], bufB[t*BLOCK+tid], bufC[t*BLOCK+tid], xin0);
        cvt_in(lbufA[t+1], lbufB[t+1], lbufC[t+1], xin1);
        gru_step2<10>(wih4, whhr, bA, bGn, bHn, xin0, xin1, h0, h1);
    }

    float2* o0 = (float2*)(out + (size_t)b0*10);
    o0[0] = make_float2(hf0[0], hf0[1]);
    o0[1] = make_float2(hf0[2], hf0[3]);
    o0[2] = make_float2(hf0[4], h0[0]);
    o0[3] = make_float2(h0[1],  h0[2]);
    o0[4] = make_float2(h0[3],  h0[4]);
    float2* o1 = (float2*)(out + (size_t)b1*10);
    o1[0] = make_float2(hf1[0], hf1[1]);
    o1[1] = make_float2(hf1[2], hf1[3]);
    o1[2] = make_float2(hf1[4], h1[0]);
    o1[3] = make_float2(h1[1],  h1[2]);
    o1[4] = make_float2(h1[3],  h1[4]);
}

extern "C" void kernel_launch(void* const* d_in, const int* in_sizes, int n_in,
                              void* d_out, int out_size)
{
    (void)in_sizes; (void)n_in; (void)out_size;
    // 9728 (weights) + 30*64*(8+8+4) = 48128 B -> 4 blocks/SM, 8 warps/SM, 512 elems/SM
    const size_t smem = (size_t)WTOT*4 + (size_t)TSTEPS*BLOCK*(8+8+4);
    cudaFuncSetAttribute(gru_kernel, cudaFuncAttributeMaxDynamicSharedMemorySize, (int)smem);
    gru_kernel<<<NBATCH/(2*BLOCK), BLOCK, smem>>>(
        (const float*)d_in[0],
        (const float*)d_in[1], (const float*)d_in[2],
        (const float*)d_in[3], (const float*)d_in[4],
        (const float*)d_in[5], (const float*)d_in[6],
        (const float*)d_in[7], (const float*)d_in[8],
        (float*)d_out);
}

// round 7
// speedup vs baseline: 1.1279x; 1.1279x over previous
#include <cuda_runtime.h>
#include <cuda_fp16.h>

#define TSTEPS 30
#define BLOCK  64
#define NBATCH 262144

// per-combo smem floats: D=1 -> 8(wih-fp16) + 80(whh) + 32(bias) = 120 (stride 128)
//                        D=10 -> 80 + 80 + 32 = 192 (stride 192)
constexpr int WTOT = 256 + 8*192;     // 1792 floats = 7168 B

typedef unsigned long long u64;
typedef unsigned int       u32;

// ---------- packed fp32x2 helpers (sm_103a FFMA2 path) ----------
__device__ __forceinline__ u64 ffma2(u64 a, u64 b, u64 c) {
    u64 d; asm("fma.rn.f32x2 %0, %1, %2, %3;" : "=l"(d) : "l"(a), "l"(b), "l"(c)); return d;
}
__device__ __forceinline__ u64 splat2(float v) {
    u64 d; asm("mov.b64 %0, {%1, %1};" : "=l"(d) : "f"(v)); return d;
}
__device__ __forceinline__ u64 pack2(float x, float y) {
    u64 d; asm("mov.b64 %0, {%1, %2};" : "=l"(d) : "f"(x), "f"(y)); return d;
}
__device__ __forceinline__ float2 unpack2(u64 v) {
    float2 r; asm("mov.b64 {%0, %1}, %2;" : "=f"(r.x), "=f"(r.y) : "l"(v)); return r;
}
__device__ __forceinline__ float tanhfast(float x){ float r; asm("tanh.approx.f32 %0, %1;" : "=f"(r) : "f"(x)); return r; }

__device__ __forceinline__ int comboOff(int c){ return c < 2 ? c*128 : 256 + (c-2)*192; }

union H4 { u64 u; u32 w[2]; __half2 h[2]; };
union H2 { u32 u; __half2 h; };
__device__ __forceinline__ u64 h4pack(__half2 a, __half2 b){ H4 t; t.h[0]=a; t.h[1]=b; return t.u; }
__device__ __forceinline__ u32 h2pack(float x, float y){ H2 t; t.h = __floats2half2_rn(x,y); return t.u; }
__device__ __forceinline__ float2 h2f(u32 v){ H2 t; t.u = v; return __half22float2(t.h); }
__device__ __forceinline__ u64 h2f2(u32 v){ float2 f = h2f(v); return pack2(f.x, f.y); }

// Slot order (rz-merged): s=2u+g, g in {r,z}, unit u (s<10); s=10..14 n-gate; s=15 pad.
// r/z rows scaled 0.5 (gi+gh merged): sig(v)=0.5+0.5*tanh(v/2); n rows unscaled.

// ---------- per-direction constants: W_hh (5x16 fp32) + biases in registers ----------
__device__ __forceinline__ void load_dir(const float* wbase, int D,
                                         u64* whhr, u64* bA, u64* bGn, u64* bHn)
{
    const float4* wh4 = (const float4*)(wbase + 8*D);
#pragma unroll
    for (int k = 0; k < 5; ++k)
#pragma unroll
        for (int qq = 0; qq < 4; ++qq) {
            float4 a = wh4[k*4+qq];
            whhr[k*8+qq*2+0] = pack2(a.x, a.y);
            whhr[k*8+qq*2+1] = pack2(a.z, a.w);
        }
    const float4* b4 = (const float4*)(wbase + 8*D + 80);    // gi-side bias
    float4 c0 = b4[0], c1 = b4[1], c2 = b4[2], c3 = b4[3];
    bA[0] = pack2(c0.x,c0.y); bA[1] = pack2(c0.z,c0.w);
    bA[2] = pack2(c1.x,c1.y); bA[3] = pack2(c1.z,c1.w);
    bA[4] = pack2(c2.x,c2.y);
    bGn[0] = pack2(c2.z,c2.w); bGn[1] = pack2(c3.x,c3.y); bGn[2] = pack2(c3.z,c3.w);
    const float4* b5 = (const float4*)(wbase + 8*D + 96);    // gh-side n bias
    float4 d2 = b5[2], d3 = b5[3];
    bHn[0] = pack2(d2.z,d2.w); bHn[1] = pack2(d3.x,d3.y); bHn[2] = pack2(d3.z,d3.w);
}

// ---------- one GRU timestep: wih streamed from smem as fp16 (2 LDS.128/k) ----------
template<int D>
__device__ __forceinline__ void gru_step(const uint4* __restrict__ wihq,
                                         const u64* whhr, const u64* bA,
                                         const u64* bGn, const u64* bHn,
                                         const float* xin, float* h)
{
    u64 A[5], Gn[3], Hn[3];
#pragma unroll
    for (int p = 0; p < 5; ++p) A[p] = bA[p];
#pragma unroll
    for (int p = 0; p < 3; ++p) { Gn[p] = bGn[p]; Hn[p] = bHn[p]; }
#pragma unroll
    for (int k = 0; k < D; ++k) {
        u64 xs = splat2(xin[k]);
        uint4 q0 = wihq[2*k+0];            // halfs: slots 0..7
        uint4 q1 = wihq[2*k+1];            // halfs: slots 8..15
        A[0]  = ffma2(h2f2(q0.x), xs, A[0]);
        A[1]  = ffma2(h2f2(q0.y), xs, A[1]);
        A[2]  = ffma2(h2f2(q0.z), xs, A[2]);
        A[3]  = ffma2(h2f2(q0.w), xs, A[3]);
        A[4]  = ffma2(h2f2(q1.x), xs, A[4]);
        Gn[0] = ffma2(h2f2(q1.y), xs, Gn[0]);
        Gn[1] = ffma2(h2f2(q1.z), xs, Gn[1]);
        Gn[2] = ffma2(h2f2(q1.w), xs, Gn[2]);
    }
#pragma unroll
    for (int k = 0; k < 5; ++k) {
        u64 hs = splat2(h[k]);
        A[0]  = ffma2(whhr[k*8+0], hs, A[0]);
        A[1]  = ffma2(whhr[k*8+1], hs, A[1]);
        A[2]  = ffma2(whhr[k*8+2], hs, A[2]);
        A[3]  = ffma2(whhr[k*8+3], hs, A[3]);
        A[4]  = ffma2(whhr[k*8+4], hs, A[4]);
        Hn[0] = ffma2(whhr[k*8+5], hs, Hn[0]);
        Hn[1] = ffma2(whhr[k*8+6], hs, Hn[1]);
        Hn[2] = ffma2(whhr[k*8+7], hs, Hn[2]);
    }
    float gn[6], hn[6];
#pragma unroll
    for (int p = 0; p < 3; ++p) {
        float2 a = unpack2(Gn[p]); gn[2*p] = a.x; gn[2*p+1] = a.y;
        float2 c = unpack2(Hn[p]); hn[2*p] = c.x; hn[2*p+1] = c.y;
    }
#pragma unroll
    for (int u = 0; u < 5; ++u) {
        float2 rz = unpack2(A[u]);                   // pre-scaled by 0.5
        float r  = fmaf(0.5f, tanhfast(rz.x), 0.5f);
        float z  = fmaf(0.5f, tanhfast(rz.y), 0.5f);
        float nn = tanhfast(fmaf(r, hn[u], gn[u]));
        h[u] = fmaf(z, h[u] - nn, nn);
    }
}

// fp16 entry (uint4 + u32) -> 10 floats (fwd 0..4, bwd 5..9)
__device__ __forceinline__ void cvt_in(uint4 q, u32 rc, float* xin)
{
    float2 p0 = h2f(q.x);
    float2 p1 = h2f(q.y);
    float2 p2 = h2f(q.z);
    float2 p3 = h2f(q.w);
    float2 p4 = h2f(rc);
    xin[0]=p0.x; xin[1]=p0.y; xin[2]=p1.x; xin[3]=p1.y; xin[4]=p2.x;
    xin[5]=p2.y; xin[6]=p3.x; xin[7]=p3.y; xin[8]=p4.x; xin[9]=p4.y;
}

// merge fwd-staged (fa = f0..f3, fcu = {f4,_}) with bwd h -> entry
__device__ __forceinline__ void pack_entry(const float* hb, u64 fa, u32 fcu,
                                           uint4& oq, u32& oc)
{
    H4 t; t.u = fa;
    H2 fc; fc.u = fcu;
    oq.x = t.w[0];
    oq.y = t.w[1];
    H2 z; z.h = __halves2half2(__low2half(fc.h), __float2half_rn(hb[0]));
    oq.z = z.u;
    oq.w = h2pack(hb[1], hb[2]);
    oc   = h2pack(hb[3], hb[4]);
}

__global__ void __launch_bounds__(BLOCK, 4)
gru_kernel(const float* __restrict__ x,
           const float* __restrict__ wih0, const float* __restrict__ whh0,
           const float* __restrict__ bih0, const float* __restrict__ bhh0,
           const float* __restrict__ wihU, const float* __restrict__ whhU,
           const float* __restrict__ bihU, const float* __restrict__ bhhU,
           float* __restrict__ out)
{
    extern __shared__ float smem[];
    float* sw    = smem;                                   // [WTOT] prepped weights
    uint4* bufQ  = (uint4*)(smem + WTOT);                  // [T*BLOCK] (f0..f4 + b0..b2)
    u32*   bufC  = (u32*)(bufQ + TSTEPS*BLOCK);            // [T*BLOCK] (b3,b4)
    const int tid = threadIdx.x;

    // ---- cooperative weight prep: wih -> fp16 slots, whh/bias -> fp32, pre-scale ----
    for (int c = 0; c < 10; ++c) {
        int l = c >> 1, d = c & 1;
        int D = l ? 10 : 1;
        float* wb = sw + comboOff(c);
        __half* wH = (__half*)wb;                           // wihT[k][slot] fp16
        for (int i = tid; i < 16*D; i += BLOCK) {
            int k = i >> 4, s = i & 15;
            float v = 0.f;
            if (s < 15) {
                int  j  = (s < 10) ? ((s & 1)*5 + (s >> 1)) : s;
                float sc = (s < 10) ? 0.5f : 1.0f;
                v = sc * (l == 0 ? wih0[d*15 + j]
                                 : wihU[(((l-1)*2 + d)*15 + j)*10 + k]);
            }
            wH[i] = __float2half_rn(v);
        }
        float* wh = wb + 8*D;                               // whhT[k][slot] fp32
        for (int i = tid; i < 80; i += BLOCK) {
            int k = i >> 4, s = i & 15;
            float v = 0.f;
            if (s < 15) {
                int  j  = (s < 10) ? ((s & 1)*5 + (s >> 1)) : s;
                float sc = (s < 10) ? 0.5f : 1.0f;
                v = sc * (l == 0 ? whh0[(d*15 + j)*5 + k]
                                 : whhU[(((l-1)*2 + d)*15 + j)*5 + k]);
            }
            wh[i] = v;
        }
        float* bg = wh + 80;                                // gi-side bias
        for (int s = tid; s < 16; s += BLOCK) {
            float v = 0.f;
            if (s < 15) {
                int  j  = (s < 10) ? ((s & 1)*5 + (s >> 1)) : s;
                float sc = (s < 10) ? 0.5f : 1.0f;
                float bi = l == 0 ? bih0[d*15 + j] : bihU[((l-1)*2 + d)*15 + j];
                float bh = l == 0 ? bhh0[d*15 + j] : bhhU[((l-1)*2 + d)*15 + j];
                v = sc * (s < 10 ? (bi + bh) : bi);
            }
            bg[s] = v;
        }
        float* bh2 = bg + 16;                               // gh-side n bias
        for (int s = tid; s < 16; s += BLOCK) {
            float v = 0.f;
            if (s >= 10 && s < 15)
                v = l == 0 ? bhh0[d*15 + s] : bhhU[((l-1)*2 + d)*15 + s];
            bh2[s] = v;
        }
    }
    __syncthreads();
    // buffer slots are thread-private from here on; no further syncs needed

    const int b = blockIdx.x * BLOCK + tid;
    const float* xrow = x + (size_t)b * TSTEPS;

    u64 whhr[40], bA[5], bGn[3], bHn[3];
    float h[5];
    u64 fscrA[TSTEPS];        // local: (f0..f3) fp16
    u32 fscrC[TSTEPS];        // local: (f4,pad) fp16

    // ===== layer 0 (D=1): fwd -> fscr, bwd -> merged write to smem buf =====
    {
        const float* w = sw + comboOff(0);
        load_dir(w, 1, whhr, bA, bGn, bHn);
        const uint4* wq = (const uint4*)w;
#pragma unroll
        for (int u = 0; u < 5; ++u) h[u] = 0.f;
#pragma unroll 1
        for (int t = 0; t < TSTEPS; ++t) {
            float xin[1] = { xrow[t] };
            gru_step<1>(wq, whhr, bA, bGn, bHn, xin, h);
            fscrA[t] = h4pack(__floats2half2_rn(h[0], h[1]), __floats2half2_rn(h[2], h[3]));
            fscrC[t] = h2pack(h[4], 0.f);
        }
    }
    {
        const float* w = sw + comboOff(1);
        load_dir(w, 1, whhr, bA, bGn, bHn);
        const uint4* wq = (const uint4*)w;
#pragma unroll
        for (int u = 0; u < 5; ++u) h[u] = 0.f;
#pragma unroll 1
        for (int tt = 0; tt < TSTEPS; ++tt) {
            int t = TSTEPS-1-tt;
            u64 fa = fscrA[t]; u32 fc = fscrC[t];          // early load (cover latency)
            float xin[1] = { xrow[t] };
            gru_step<1>(wq, whhr, bA, bGn, bHn, xin, h);
            uint4 oq; u32 oc;
            pack_entry(h, fa, fc, oq, oc);
            bufQ[t*BLOCK+tid] = oq; bufC[t*BLOCK+tid] = oc;
        }
    }

    // ===== layers 1..3: fwd stages into fscr, bwd overwrites smem buf in place =====
#pragma unroll 1
    for (int l = 1; l < 4; ++l) {
        {   // fwd
            const float* w = sw + comboOff(2*l);
            load_dir(w, 10, whhr, bA, bGn, bHn);
            const uint4* wq = (const uint4*)w;
#pragma unroll
            for (int u = 0; u < 5; ++u) h[u] = 0.f;
#pragma unroll 1
            for (int t = 0; t < TSTEPS; ++t) {
                float xin[10];
                cvt_in(bufQ[t*BLOCK+tid], bufC[t*BLOCK+tid], xin);
                gru_step<10>(wq, whhr, bA, bGn, bHn, xin, h);
                fscrA[t] = h4pack(__floats2half2_rn(h[0], h[1]), __floats2half2_rn(h[2], h[3]));
                fscrC[t] = h2pack(h[4], 0.f);
            }
        }
        {   // bwd; fscr loaded at top of step (~full step of latency cover)
            const float* w = sw + comboOff(2*l+1);
            load_dir(w, 10, whhr, bA, bGn, bHn);
            const uint4* wq = (const uint4*)w;
#pragma unroll
            for (int u = 0; u < 5; ++u) h[u] = 0.f;
#pragma unroll 1
            for (int tt = 0; tt < TSTEPS; ++tt) {
                int t = TSTEPS-1-tt;
                u64 fa = fscrA[t]; u32 fc = fscrC[t];
                float xin[10];
                cvt_in(bufQ[t*BLOCK+tid], bufC[t*BLOCK+tid], xin);
                gru_step<10>(wq, whhr, bA, bGn, bHn, xin, h);
                uint4 oq; u32 oc;
                pack_entry(h, fa, fc, oq, oc);
                bufQ[t*BLOCK+tid] = oq; bufC[t*BLOCK+tid] = oc;
            }
        }
    }

    // ===== layer 4: fwd full (keep final h only); bwd = ONE step at t=T-1 =====
    float hf[5];
    {
        const float* w = sw + comboOff(8);
        load_dir(w, 10, whhr, bA, bGn, bHn);
        const uint4* wq = (const uint4*)w;
#pragma unroll
        for (int u = 0; u < 5; ++u) h[u] = 0.f;
#pragma unroll 1
        for (int t = 0; t < TSTEPS; ++t) {
            float xin[10];
            cvt_in(bufQ[t*BLOCK+tid], bufC[t*BLOCK+tid], xin);
            gru_step<10>(wq, whhr, bA, bGn, bHn, xin, h);
        }
#pragma unroll
        for (int u = 0; u < 5; ++u) hf[u] = h[u];
    }
    {
        const float* w = sw + comboOff(9);
        load_dir(w, 10, whhr, bA, bGn, bHn);
        const uint4* wq = (const uint4*)w;
#pragma unroll
        for (int u = 0; u < 5; ++u) h[u] = 0.f;
        float xin[10];
        int t = TSTEPS-1;
        cvt_in(bufQ[t*BLOCK+tid], bufC[t*BLOCK+tid], xin);
        gru_step<10>(wq, whhr, bA, bGn, bHn, xin, h);
    }

    float2* o2 = (float2*)(out + (size_t)b*10);
    o2[0] = make_float2(hf[0], hf[1]);
    o2[1] = make_float2(hf[2], hf[3]);
    o2[2] = make_float2(hf[4], h[0]);
    o2[3] = make_float2(h[1],  h[2]);
    o2[4] = make_float2(h[3],  h[4]);
}

extern "C" void kernel_launch(void* const* d_in, const int* in_sizes, int n_in,
                              void* d_out, int out_size)
{
    (void)in_sizes; (void)n_in; (void)out_size;
    // 7168 (weights) + 30*64*16 (bufQ) + 30*64*4 (bufC) = 45568 B -> 4 blocks/SM
    const size_t smem = (size_t)WTOT*4 + (size_t)TSTEPS*BLOCK*(16+4);
    cudaFuncSetAttribute(gru_kernel, cudaFuncAttributeMaxDynamicSharedMemorySize, (int)smem);
    gru_kernel<<<NBATCH/BLOCK, BLOCK, smem>>>(
        (const float*)d_in[0],
        (const float*)d_in[1], (const float*)d_in[2],
        (const float*)d_in[3], (const float*)d_in[4],
        (const float*)d_in[5], (const float*)d_in[6],
        (const float*)d_in[7], (const float*)d_in[8],
        (float*)d_out);
}